// round 13
// baseline (speedup 1.0000x reference)
#include <cuda_runtime.h>
#include <cuda_bf16.h>
#include <cstdint>

// Problem constants
#define Bn    8
#define NN    2048
#define FINx  512
#define FOUTx 256
#define MTOT  (Bn*NN)          // 16384
#define ALPHAc 0.2f
#define NEGc  (-9e15f)

// ---------------- scratch (device globals: allocation-free) ----------------
__device__ float g_h [MTOT*FOUTx];            // feat@W
__device__ float g_h1[MTOT*FOUTx];            // feat@W1
__device__ float g_g [MTOT*FOUTx];            // h@a12
__device__ float g_h2[MTOT*FOUTx];            // fa@W2
__device__ float g_Ax[MTOT];
__device__ float g_Ay[MTOT];
__device__ float g_e1[MTOT*8];
__device__ float g_e2[MTOT*8];
__device__ float g_S [(size_t)Bn*NN*NN];      // logits (134 MB)
__device__ __nv_bfloat16 g_Shi[(size_t)Bn*NN*NN];   // probs hi (67 MB)
__device__ __nv_bfloat16 g_Slo[(size_t)Bn*NN*NN];   // probs lo (67 MB)
__device__ __nv_bfloat16 g_Fhi[(size_t)Bn*FINx*NN]; // featT hi (16 MB)
__device__ __nv_bfloat16 g_Flo[(size_t)Bn*FINx*NN]; // featT lo (16 MB)
__device__ __nv_bfloat16 g_fRhi[(size_t)MTOT*FINx]; // feat row-major hi
__device__ __nv_bfloat16 g_fRlo[(size_t)MTOT*FINx];
__device__ __nv_bfloat16 g_fahi[(size_t)MTOT*FINx]; // fa hi
__device__ __nv_bfloat16 g_falo[(size_t)MTOT*FINx];
__device__ __nv_bfloat16 g_ghi[MTOT*FOUTx];   // g hi
__device__ __nv_bfloat16 g_glo[MTOT*FOUTx];
__device__ __nv_bfloat16 g_hhi[MTOT*FOUTx];   // h hi
__device__ __nv_bfloat16 g_hlo[MTOT*FOUTx];
__device__ __nv_bfloat16 g_Wth [FOUTx*FINx];  // W^T hi/lo
__device__ __nv_bfloat16 g_Wtl [FOUTx*FINx];
__device__ __nv_bfloat16 g_W1th[FOUTx*FINx];
__device__ __nv_bfloat16 g_W1tl[FOUTx*FINx];
__device__ __nv_bfloat16 g_W2th[FOUTx*FINx];
__device__ __nv_bfloat16 g_W2tl[FOUTx*FINx];
__device__ __nv_bfloat16 g_a12th[FOUTx*FOUTx];
__device__ __nv_bfloat16 g_a12tl[FOUTx*FOUTx];
__device__ float g_fa[(size_t)MTOT*FINx];     // feat_agg

// ---------------- mma.sync / cp.async helpers (sm_80+) ----------------------
__device__ __forceinline__ uint32_t smem_u32(const void* p) {
    return (uint32_t)__cvta_generic_to_shared(p);
}
__device__ __forceinline__ void cp16(uint32_t s, const void* g) {
    asm volatile("cp.async.cg.shared.global [%0], [%1], 16;" :: "r"(s), "l"(g));
}
__device__ __forceinline__ void ldmx4(uint32_t* d, uint32_t a) {
    asm volatile("ldmatrix.sync.aligned.m8n8.x4.shared.b16 {%0,%1,%2,%3}, [%4];"
                 : "=r"(d[0]), "=r"(d[1]), "=r"(d[2]), "=r"(d[3]) : "r"(a));
}
__device__ __forceinline__ void mma_bf16(float* c, const uint32_t* a,
                                         uint32_t b0, uint32_t b1) {
    asm volatile("mma.sync.aligned.m16n8k16.row.col.f32.bf16.bf16.f32 "
                 "{%0,%1,%2,%3}, {%4,%5,%6,%7}, {%8,%9}, {%0,%1,%2,%3};"
                 : "+f"(c[0]), "+f"(c[1]), "+f"(c[2]), "+f"(c[3])
                 : "r"(a[0]), "r"(a[1]), "r"(a[2]), "r"(a[3]), "r"(b0), "r"(b1));
}
__device__ __forceinline__ float lrelu(float v) {
    return (v > 0.f) ? v : ALPHAc * v;
}
// polynomial exp (FMA pipe, avoids MUFU bottleneck); x <= 0, abs err ~1e-7 rel
__device__ __forceinline__ float fast_exp(float x) {
    float t = x * 1.44269504088896f;        // log2(e)
    t = fmaxf(t, -126.0f);
    const float n = rintf(t);
    const float f = t - n;                  // [-0.5, 0.5]
    float p = 1.5403530394e-4f;             // ln2^6/720
    p = fmaf(p, f, 1.3333558146e-3f);       // ln2^5/120
    p = fmaf(p, f, 9.6181291076e-3f);       // ln2^4/24
    p = fmaf(p, f, 5.5504108664e-2f);       // ln2^3/6
    p = fmaf(p, f, 2.4022650696e-1f);       // ln2^2/2
    p = fmaf(p, f, 6.9314718056e-1f);       // ln2
    p = fmaf(p, f, 1.0f);
    const int e = (int)n;
    return __int_as_float((e + 127) << 23) * p;
}
__device__ __forceinline__ void split_bf16(float v, __nv_bfloat16& h, __nv_bfloat16& l) {
    h = __float2bfloat16_rn(v);
    l = __float2bfloat16_rn(v - __bfloat162float(h));
}

// ---------------- HMMA GEMM: C = A @ B^T (bf16 3-pass split) ---------------
// CTA tile 128(M) x 128(N), 256 threads = 8 warps (4m x 2n), warp tile 32x64.
// A = [MA,K] row-major hi/lo, B = [NB,K] K-contig hi/lo, batch via blockIdx.z.
// EPI==0: fp32 store. EPI==1: scores epilogue. EPI==2: fp32 + bf16 hi/lo split.
#define AGG_ROWB  80                   // smem row stride in bytes (40 bf16)
#define AGG_ARR   10240                // one 128x40-bf16 array
#define AGG_BUF   (4*AGG_ARR)          // Ah,Al,Bh,Bl
#define AGG_SMEM  (2*AGG_BUF)          // double buffer = 80 KB

template<int EPI>
__global__ void __launch_bounds__(256)
mma_gemm_k(const __nv_bfloat16* __restrict__ Ah, const __nv_bfloat16* __restrict__ Al,
           const __nv_bfloat16* __restrict__ Bh, const __nv_bfloat16* __restrict__ Bl,
           float* __restrict__ C, int K, int MA, int NB, int ldc,
           const float* __restrict__ Ax, const float* __restrict__ Ay,
           const int* __restrict__ adj,
           __nv_bfloat16* __restrict__ Chi, __nv_bfloat16* __restrict__ Clo)
{
    extern __shared__ char smem[];
    const uint32_t sbase = smem_u32(smem);
    const int tid  = threadIdx.x;
    const int wid  = tid >> 5;
    const int lane = tid & 31;
    const int b  = blockIdx.z;
    const int m0 = blockIdx.y * 128;
    const int n0 = blockIdx.x * 128;

    const int r   = tid >> 2;
    const int seg = tid & 3;
    const __nv_bfloat16* gAh = Ah + ((size_t)b * MA + m0 + r) * K + seg * 8;
    const __nv_bfloat16* gAl = Al + ((size_t)b * MA + m0 + r) * K + seg * 8;
    const __nv_bfloat16* gBh = Bh + ((size_t)b * NB + n0 + r) * K + seg * 8;
    const __nv_bfloat16* gBl = Bl + ((size_t)b * NB + n0 + r) * K + seg * 8;
    const uint32_t sA = r * AGG_ROWB + seg * 16;
    const size_t  gstep = (size_t)64 * K;

    #define AGG_ISSUE(bufi, kc) do {                                           \
        const int kofs = (kc) * 32;                                            \
        uint32_t s0 = sbase + (bufi) * AGG_BUF + sA;                            \
        cp16(s0 + 0*AGG_ARR,               gAh + kofs);                         \
        cp16(s0 + 1*AGG_ARR,               gAl + kofs);                         \
        cp16(s0 + 2*AGG_ARR,               gBh + kofs);                         \
        cp16(s0 + 3*AGG_ARR,               gBl + kofs);                         \
        uint32_t s1 = s0 + 64 * AGG_ROWB;                                       \
        cp16(s1 + 0*AGG_ARR,               gAh + gstep + kofs);                 \
        cp16(s1 + 1*AGG_ARR,               gAl + gstep + kofs);                 \
        cp16(s1 + 2*AGG_ARR,               gBh + gstep + kofs);                 \
        cp16(s1 + 3*AGG_ARR,               gBl + gstep + kofs);                 \
        asm volatile("cp.async.commit_group;" ::: "memory");                    \
    } while (0)

    const int wm = wid & 3;
    const int wn = wid >> 2;

    float acc[2][8][4];
    #pragma unroll
    for (int mi = 0; mi < 2; mi++)
        #pragma unroll
        for (int nj = 0; nj < 8; nj++)
            #pragma unroll
            for (int q = 0; q < 4; q++) acc[mi][nj][q] = 0.f;

    const int NC = K / 32;
    AGG_ISSUE(0, 0);
    int buf = 0;
    for (int kc = 0; kc < NC; kc++) {
        if (kc + 1 < NC) {
            AGG_ISSUE(buf ^ 1, kc + 1);
            asm volatile("cp.async.wait_group 1;" ::: "memory");
        } else {
            asm volatile("cp.async.wait_group 0;" ::: "memory");
        }
        __syncthreads();

        const uint32_t base = sbase + buf * AGG_BUF;
        #pragma unroll
        for (int kq = 0; kq < 2; kq++) {
            const uint32_t aaddr = base
                + (uint32_t)((wm * 32 + (lane & 15)) * AGG_ROWB)
                + (uint32_t)((kq * 16 + (lane >> 4) * 8) * 2);
            uint32_t ah0[4], ah1[4], al0[4], al1[4];
            ldmx4(ah0, aaddr);
            ldmx4(ah1, aaddr + 16 * AGG_ROWB);
            ldmx4(al0, aaddr + 1*AGG_ARR);
            ldmx4(al1, aaddr + 1*AGG_ARR + 16 * AGG_ROWB);

            #pragma unroll
            for (int np = 0; np < 4; np++) {
                const uint32_t baddr = base + 2*AGG_ARR
                    + (uint32_t)((wn * 64 + np * 16 + (lane & 7) + ((lane >> 4) << 3)) * AGG_ROWB)
                    + (uint32_t)((kq * 16 + ((lane >> 3) & 1) * 8) * 2);
                uint32_t bh[4], bl[4];
                ldmx4(bh, baddr);
                ldmx4(bl, baddr + 1*AGG_ARR);
                const int j0 = np * 2, j1 = np * 2 + 1;
                mma_bf16(acc[0][j0], ah0, bh[0], bh[1]);
                mma_bf16(acc[0][j1], ah0, bh[2], bh[3]);
                mma_bf16(acc[1][j0], ah1, bh[0], bh[1]);
                mma_bf16(acc[1][j1], ah1, bh[2], bh[3]);
                mma_bf16(acc[0][j0], ah0, bl[0], bl[1]);
                mma_bf16(acc[0][j1], ah0, bl[2], bl[3]);
                mma_bf16(acc[1][j0], ah1, bl[0], bl[1]);
                mma_bf16(acc[1][j1], ah1, bl[2], bl[3]);
                mma_bf16(acc[0][j0], al0, bh[0], bh[1]);
                mma_bf16(acc[0][j1], al0, bh[2], bh[3]);
                mma_bf16(acc[1][j0], al1, bh[0], bh[1]);
                mma_bf16(acc[1][j1], al1, bh[2], bh[3]);
            }
        }
        __syncthreads();
        buf ^= 1;
    }
    #undef AGG_ISSUE

    // epilogue
    const int mbase = m0 + wm * 32;
    const int nbase = n0 + wn * 64;
    #pragma unroll
    for (int mi = 0; mi < 2; mi++) {
        #pragma unroll
        for (int nj = 0; nj < 8; nj++) {
            const int mm = mbase + mi * 16 + (lane >> 2);
            const int nc = nbase + nj * 8 + (lane & 3) * 2;
            const size_t i0 = ((size_t)b * MA + mm) * ldc + nc;
            float* d0 = C + i0;
            if (EPI == 0) {
                *(float2*)d0              = make_float2(acc[mi][nj][0], acc[mi][nj][1]);
                *(float2*)(d0 + 8 * ldc)  = make_float2(acc[mi][nj][2], acc[mi][nj][3]);
            } else if (EPI == 2) {
                const float2 v0 = make_float2(acc[mi][nj][0], acc[mi][nj][1]);
                const float2 v1 = make_float2(acc[mi][nj][2], acc[mi][nj][3]);
                *(float2*)d0              = v0;
                *(float2*)(d0 + 8 * ldc)  = v1;
                __nv_bfloat162 H0, L0, H1, L1;
                split_bf16(v0.x, H0.x, L0.x); split_bf16(v0.y, H0.y, L0.y);
                split_bf16(v1.x, H1.x, L1.x); split_bf16(v1.y, H1.y, L1.y);
                *(__nv_bfloat162*)(Chi + i0)            = H0;
                *(__nv_bfloat162*)(Clo + i0)            = L0;
                *(__nv_bfloat162*)(Chi + i0 + 8 * ldc)  = H1;
                *(__nv_bfloat162*)(Clo + i0 + 8 * ldc)  = L1;
            } else {
                const float2 axv = *(const float2*)(Ax + b * NN + nc);
                const float ay0 = Ay[b * NN + mm];
                const float ay1 = Ay[b * NN + mm + 8];
                float2 v0 = make_float2(lrelu(acc[mi][nj][0] + ay0 + axv.x),
                                        lrelu(acc[mi][nj][1] + ay0 + axv.y));
                float2 v1 = make_float2(lrelu(acc[mi][nj][2] + ay1 + axv.x),
                                        lrelu(acc[mi][nj][3] + ay1 + axv.y));
                const int* adp = adj + ((size_t)b * NN + mm) * NN + nc;
                int2 a0v = *(const int2*)adp;
                int2 a1v = *(const int2*)(adp + 8 * NN);
                v0.x = (a0v.x > 0) ? v0.x : NEGc;
                v0.y = (a0v.y > 0) ? v0.y : NEGc;
                v1.x = (a1v.x > 0) ? v1.x : NEGc;
                v1.y = (a1v.y > 0) ? v1.y : NEGc;
                *(float2*)d0             = v0;
                *(float2*)(d0 + 8 * ldc) = v1;
            }
        }
    }
}

// --------- fp32 -> bf16 hi/lo elementwise split ------------------------------
__global__ void split_k(const float* __restrict__ src,
                        __nv_bfloat16* __restrict__ hi,
                        __nv_bfloat16* __restrict__ lo, size_t n4)
{
    const size_t i = (size_t)blockIdx.x * blockDim.x + threadIdx.x;
    if (i >= n4) return;
    const float4 v = ((const float4*)src)[i];
    __nv_bfloat162 H0, L0, H1, L1;
    split_bf16(v.x, H0.x, L0.x); split_bf16(v.y, H0.y, L0.y);
    split_bf16(v.z, H1.x, L1.x); split_bf16(v.w, H1.y, L1.y);
    ((__nv_bfloat162*)hi)[i*2]   = H0;
    ((__nv_bfloat162*)hi)[i*2+1] = H1;
    ((__nv_bfloat162*)lo)[i*2]   = L0;
    ((__nv_bfloat162*)lo)[i*2+1] = L1;
}

// --------- generic transpose + split: dst[c][r] = split(src[r][c]) ----------
__global__ void tsplit_k(const float* __restrict__ src,
                         __nv_bfloat16* __restrict__ hi,
                         __nv_bfloat16* __restrict__ lo, int R, int C)
{
    __shared__ float t[32][33];
    const int r0 = blockIdx.y * 32;
    const int c0 = blockIdx.x * 32;
    const int tx = threadIdx.x, ty = threadIdx.y;   // (32, 8)
    #pragma unroll
    for (int i = 0; i < 4; i++)
        t[ty + 8*i][tx] = src[(size_t)(r0 + ty + 8*i) * C + c0 + tx];
    __syncthreads();
    #pragma unroll
    for (int i = 0; i < 4; i++) {
        const float v = t[tx][ty + 8*i];
        __nv_bfloat16 h, l;
        split_bf16(v, h, l);
        const size_t idx = (size_t)(c0 + ty + 8*i) * R + r0 + tx;
        hi[idx] = h;
        lo[idx] = l;
    }
}

// --------- batched transpose + split: featT[b][f][n] = split(feat[b][n][f]) -
__global__ void transpose_split_k(const float* __restrict__ feat,
                                  __nv_bfloat16* __restrict__ Fhi,
                                  __nv_bfloat16* __restrict__ Flo)
{
    __shared__ float t[32][33];
    const int b  = blockIdx.z;
    const int n0 = blockIdx.x * 32;
    const int f0 = blockIdx.y * 32;
    const int tx = threadIdx.x, ty = threadIdx.y;   // (32, 8)

    #pragma unroll
    for (int i = 0; i < 4; i++)
        t[ty + 8*i][tx] = feat[((size_t)b * NN + n0 + ty + 8*i) * FINx + f0 + tx];
    __syncthreads();
    #pragma unroll
    for (int i = 0; i < 4; i++) {
        const float v = t[tx][ty + 8*i];
        __nv_bfloat16 h, l;
        split_bf16(v, h, l);
        const size_t idx = ((size_t)b * FINx + f0 + ty + 8*i) * NN + n0 + tx;
        Fhi[idx] = h;
        Flo[idx] = l;
    }
}

// --------- Ax = h@a1, Ay = h@a2, e1[e] = feat row . L_w[e] (warp/row) -------
__global__ void small1_k(const float* __restrict__ h, const float* __restrict__ feat,
                         const float* __restrict__ a1, const float* __restrict__ a2,
                         const float* __restrict__ Lw,
                         float* __restrict__ Ax, float* __restrict__ Ay,
                         float* __restrict__ e1)
{
    const int warp = (blockIdx.x * blockDim.x + threadIdx.x) >> 5;
    const int lane = threadIdx.x & 31;
    if (warp >= MTOT) return;

    const float4* hr  = (const float4*)(h + (size_t)warp * FOUTx);
    const float4* a14 = (const float4*)a1;
    const float4* a24 = (const float4*)a2;
    float sx = 0.f, sy = 0.f;
    #pragma unroll
    for (int c = 0; c < 2; c++) {
        const float4 f = hr[lane + c * 32];
        const float4 u = a14[lane + c * 32];
        const float4 w = a24[lane + c * 32];
        sx += f.x*u.x + f.y*u.y + f.z*u.z + f.w*u.w;
        sy += f.x*w.x + f.y*w.y + f.z*w.z + f.w*w.w;
    }
    const float4* fr  = (const float4*)(feat + (size_t)warp * FINx);
    const float4* Lw4 = (const float4*)Lw;
    float acc[5] = {0.f, 0.f, 0.f, 0.f, 0.f};
    #pragma unroll
    for (int c = 0; c < 4; c++) {
        const float4 f = fr[lane + c * 32];
        #pragma unroll
        for (int e = 0; e < 5; e++) {
            const float4 w = Lw4[e * 128 + lane + c * 32];
            acc[e] += f.x*w.x + f.y*w.y + f.z*w.z + f.w*w.w;
        }
    }
    #pragma unroll
    for (int off = 16; off; off >>= 1) {
        sx += __shfl_xor_sync(0xffffffffu, sx, off);
        sy += __shfl_xor_sync(0xffffffffu, sy, off);
        #pragma unroll
        for (int e = 0; e < 5; e++) acc[e] += __shfl_xor_sync(0xffffffffu, acc[e], off);
    }
    if (lane == 0) {
        Ax[warp] = sx;
        Ay[warp] = sy;
        #pragma unroll
        for (int e = 0; e < 5; e++) e1[warp * 8 + e] = acc[e];
    }
}

// --------- e2[e] = feat_agg row . R_w[e] -----------------------------------
__global__ void small2_k(const float* __restrict__ fa, const float* __restrict__ Rw,
                         float* __restrict__ e2)
{
    const int warp = (blockIdx.x * blockDim.x + threadIdx.x) >> 5;
    const int lane = threadIdx.x & 31;
    if (warp >= MTOT) return;

    const float4* fr  = (const float4*)(fa + (size_t)warp * FINx);
    const float4* Rw4 = (const float4*)Rw;
    float acc[5] = {0.f, 0.f, 0.f, 0.f, 0.f};
    #pragma unroll
    for (int c = 0; c < 4; c++) {
        const float4 f = fr[lane + c * 32];
        #pragma unroll
        for (int e = 0; e < 5; e++) {
            const float4 w = Rw4[e * 128 + lane + c * 32];
            acc[e] += f.x*w.x + f.y*w.y + f.z*w.z + f.w*w.w;
        }
    }
    #pragma unroll
    for (int off = 16; off; off >>= 1) {
        #pragma unroll
        for (int e = 0; e < 5; e++) acc[e] += __shfl_xor_sync(0xffffffffu, acc[e], off);
    }
    if (lane == 0) {
        #pragma unroll
        for (int e = 0; e < 5; e++) e2[warp * 8 + e] = acc[e];
    }
}

// --------- row softmax over N=2048 -> bf16 hi/lo probs (poly exp) -----------
__global__ void __launch_bounds__(256)
softmax_k(const float* __restrict__ S,
          __nv_bfloat16* __restrict__ Phi, __nv_bfloat16* __restrict__ Plo)
{
    const float4* p4 = (const float4*)(S + (size_t)blockIdx.x * NN);
    const int t = threadIdx.x;
    float4 va = p4[t];
    float4 vb = p4[t + 256];
    float mx = fmaxf(fmaxf(fmaxf(va.x, va.y), fmaxf(va.z, va.w)),
                     fmaxf(fmaxf(vb.x, vb.y), fmaxf(vb.z, vb.w)));

    __shared__ float red[256];
    red[t] = mx; __syncthreads();
    #pragma unroll
    for (int s = 128; s > 0; s >>= 1) {
        if (t < s) red[t] = fmaxf(red[t], red[t + s]);
        __syncthreads();
    }
    mx = red[0];
    __syncthreads();

    va.x = fast_exp(va.x - mx); va.y = fast_exp(va.y - mx);
    va.z = fast_exp(va.z - mx); va.w = fast_exp(va.w - mx);
    vb.x = fast_exp(vb.x - mx); vb.y = fast_exp(vb.y - mx);
    vb.z = fast_exp(vb.z - mx); vb.w = fast_exp(vb.w - mx);
    float sum = (va.x + va.y) + (va.z + va.w) + (vb.x + vb.y) + (vb.z + vb.w);
    red[t] = sum; __syncthreads();
    #pragma unroll
    for (int s = 128; s > 0; s >>= 1) {
        if (t < s) red[t] += red[t + s];
        __syncthreads();
    }
    const float inv = 1.0f / red[0];

    __nv_bfloat16* ph = Phi + (size_t)blockIdx.x * NN;
    __nv_bfloat16* pl = Plo + (size_t)blockIdx.x * NN;
    __nv_bfloat162 H[2], L[2];
    split_bf16(va.x * inv, H[0].x, L[0].x); split_bf16(va.y * inv, H[0].y, L[0].y);
    split_bf16(va.z * inv, H[1].x, L[1].x); split_bf16(va.w * inv, H[1].y, L[1].y);
    *(uint2*)(ph + t * 4) = *(uint2*)H;
    *(uint2*)(pl + t * 4) = *(uint2*)L;
    split_bf16(vb.x * inv, H[0].x, L[0].x); split_bf16(vb.y * inv, H[0].y, L[0].y);
    split_bf16(vb.z * inv, H[1].x, L[1].x); split_bf16(vb.w * inv, H[1].y, L[1].y);
    *(uint2*)(ph + 1024 + t * 4) = *(uint2*)H;
    *(uint2*)(pl + 1024 + t * 4) = *(uint2*)L;
}

// --------- out = h1 + h2 + e1^T B_w[o] e2 ----------------------------------
__global__ void __launch_bounds__(256)
final_k(const float* __restrict__ h1, const float* __restrict__ h2,
        const float* __restrict__ e1, const float* __restrict__ e2,
        const float* __restrict__ Bw, float* __restrict__ out)
{
    const int m = blockIdx.x;
    const int o = threadIdx.x;   // 0..255
    __shared__ float s1[8], s2[8];
    if (o < 5) { s1[o] = e1[m * 8 + o]; s2[o] = e2[m * 8 + o]; }
    __syncthreads();

    const float* bw = Bw + o * 25;
    float s = 0.f;
    #pragma unroll
    for (int i = 0; i < 5; i++) {
        const float ei = s1[i];
        #pragma unroll
        for (int j = 0; j < 5; j++) s += ei * bw[i * 5 + j] * s2[j];
    }
    const size_t idx = (size_t)m * FOUTx + o;
    out[idx] = h1[idx] + h2[idx] + s;
}

// ---------------------------------------------------------------------------
extern "C" void kernel_launch(void* const* d_in, const int* in_sizes, int n_in,
                              void* d_out, int out_size)
{
    const float* feat = (const float*)d_in[0];
    const int*   adj  = (const int*)  d_in[1];
    const float* W    = (const float*)d_in[2];
    const float* W1   = (const float*)d_in[3];
    const float* W2   = (const float*)d_in[4];
    const float* a1   = (const float*)d_in[5];
    const float* a2   = (const float*)d_in[6];
    const float* a12  = (const float*)d_in[7];
    const float* Lw   = (const float*)d_in[8];
    const float* Rw   = (const float*)d_in[9];
    const float* Bw   = (const float*)d_in[10];
    float* out = (float*)d_out;

    float *h, *h1, *g, *h2, *Ax, *Ay, *e1, *e2, *S, *fa;
    __nv_bfloat16 *Shi, *Slo, *Fhi, *Flo, *ghi, *glo, *hhi, *hlo;
    __nv_bfloat16 *fRhi, *fRlo, *fahi, *falo;
    __nv_bfloat16 *Wth, *Wtl, *W1th, *W1tl, *W2th, *W2tl, *a12th, *a12tl;
    cudaGetSymbolAddress((void**)&h,  g_h);
    cudaGetSymbolAddress((void**)&h1, g_h1);
    cudaGetSymbolAddress((void**)&g,  g_g);
    cudaGetSymbolAddress((void**)&h2, g_h2);
    cudaGetSymbolAddress((void**)&Ax, g_Ax);
    cudaGetSymbolAddress((void**)&Ay, g_Ay);
    cudaGetSymbolAddress((void**)&e1, g_e1);
    cudaGetSymbolAddress((void**)&e2, g_e2);
    cudaGetSymbolAddress((void**)&S,  g_S);
    cudaGetSymbolAddress((void**)&fa, g_fa);
    cudaGetSymbolAddress((void**)&Shi, g_Shi);
    cudaGetSymbolAddress((void**)&Slo, g_Slo);
    cudaGetSymbolAddress((void**)&Fhi, g_Fhi);
    cudaGetSymbolAddress((void**)&Flo, g_Flo);
    cudaGetSymbolAddress((void**)&ghi, g_ghi);
    cudaGetSymbolAddress((void**)&glo, g_glo);
    cudaGetSymbolAddress((void**)&hhi, g_hhi);
    cudaGetSymbolAddress((void**)&hlo, g_hlo);
    cudaGetSymbolAddress((void**)&fRhi, g_fRhi);
    cudaGetSymbolAddress((void**)&fRlo, g_fRlo);
    cudaGetSymbolAddress((void**)&fahi, g_fahi);
    cudaGetSymbolAddress((void**)&falo, g_falo);
    cudaGetSymbolAddress((void**)&Wth,  g_Wth);
    cudaGetSymbolAddress((void**)&Wtl,  g_Wtl);
    cudaGetSymbolAddress((void**)&W1th, g_W1th);
    cudaGetSymbolAddress((void**)&W1tl, g_W1tl);
    cudaGetSymbolAddress((void**)&W2th, g_W2th);
    cudaGetSymbolAddress((void**)&W2tl, g_W2tl);
    cudaGetSymbolAddress((void**)&a12th, g_a12th);
    cudaGetSymbolAddress((void**)&a12tl, g_a12tl);

    static int smem_set = 0;
    if (!smem_set) {
        cudaFuncSetAttribute(mma_gemm_k<0>, cudaFuncAttributeMaxDynamicSharedMemorySize,
                             AGG_SMEM);
        cudaFuncSetAttribute(mma_gemm_k<1>, cudaFuncAttributeMaxDynamicSharedMemorySize,
                             AGG_SMEM);
        cudaFuncSetAttribute(mma_gemm_k<2>, cudaFuncAttributeMaxDynamicSharedMemorySize,
                             AGG_SMEM);
        smem_set = 1;
    }

    const dim3 blk(256);
    const dim3 tb(32, 8);

    // weight transposes + splits (tiny)
    tsplit_k<<<dim3(FOUTx/32, FINx/32), tb>>>(W,   Wth,  Wtl,  FINx,  FOUTx);
    tsplit_k<<<dim3(FOUTx/32, FINx/32), tb>>>(W1,  W1th, W1tl, FINx,  FOUTx);
    tsplit_k<<<dim3(FOUTx/32, FINx/32), tb>>>(W2,  W2th, W2tl, FINx,  FOUTx);
    tsplit_k<<<dim3(FOUTx/32, FOUTx/32), tb>>>(a12, a12th, a12tl, FOUTx, FOUTx);

    // feat splits: row-major (A operand) + transposed (B operand for agg)
    const size_t nfeat4 = (size_t)MTOT * FINx / 4;
    split_k<<<(unsigned)((nfeat4 + 255) / 256), 256>>>(feat, fRhi, fRlo, nfeat4);
    transpose_split_k<<<dim3(NN/32, FINx/32, Bn), tb>>>(feat, Fhi, Flo);

    // h = feat @ W (fused hi/lo split) ; h1 = feat @ W1
    mma_gemm_k<2><<<dim3(FOUTx/128, MTOT/128, 1), blk, AGG_SMEM>>>(
        fRhi, fRlo, Wth, Wtl, h, FINx, MTOT, FOUTx, FOUTx, nullptr, nullptr, nullptr,
        hhi, hlo);
    mma_gemm_k<0><<<dim3(FOUTx/128, MTOT/128, 1), blk, AGG_SMEM>>>(
        fRhi, fRlo, W1th, W1tl, h1, FINx, MTOT, FOUTx, FOUTx, nullptr, nullptr, nullptr,
        nullptr, nullptr);

    // Ax, Ay, e1
    small1_k<<<MTOT/8, 256>>>(h, feat, a1, a2, Lw, Ax, Ay, e1);

    // g = h @ a12  (fused hi/lo split)
    mma_gemm_k<2><<<dim3(FOUTx/128, MTOT/128, 1), blk, AGG_SMEM>>>(
        hhi, hlo, a12th, a12tl, g, FOUTx, MTOT, FOUTx, FOUTx, nullptr, nullptr, nullptr,
        ghi, glo);

    // S = leaky(Ax+Ay+g.h^T) masked  (HMMA)
    mma_gemm_k<1><<<dim3(NN/128, NN/128, Bn), blk, AGG_SMEM>>>(
        ghi, glo, hhi, hlo, S, FOUTx, NN, NN, NN, Ax, Ay, adj, nullptr, nullptr);

    // row softmax -> bf16 hi/lo probs (poly exp)
    softmax_k<<<MTOT, 256>>>(S, Shi, Slo);

    // feat_agg = P @ feat  (fused hi/lo split)
    mma_gemm_k<2><<<dim3(FINx/128, NN/128, Bn), blk, AGG_SMEM>>>(
        Shi, Slo, Fhi, Flo, fa, NN, NN, FINx, FINx, nullptr, nullptr, nullptr,
        fahi, falo);

    // h2 = fa @ W2 (HMMA) ; e2
    mma_gemm_k<0><<<dim3(FOUTx/128, MTOT/128, 1), blk, AGG_SMEM>>>(
        fahi, falo, W2th, W2tl, h2, FINx, MTOT, FOUTx, FOUTx, nullptr, nullptr, nullptr,
        nullptr, nullptr);
    small2_k<<<MTOT/8, 256>>>(fa, Rw, e2);

    // out = h1 + h2 + bilinear(e1, B_w, e2)
    final_k<<<MTOT, 256>>>(h1, h2, e1, e2, Bw, out);
}

// round 14
// speedup vs baseline: 1.0024x; 1.0024x over previous
#include <cuda_runtime.h>
#include <cuda_bf16.h>
#include <cstdint>

// Problem constants
#define Bn    8
#define NN    2048
#define FINx  512
#define FOUTx 256
#define MTOT  (Bn*NN)          // 16384
#define ALPHAc 0.2f
#define NEGc  (-9e15f)

// ---------------- scratch (device globals: allocation-free) ----------------
__device__ float g_hh1[(size_t)MTOT*512];     // [h | h1] fused (ldc=512)
__device__ __nv_bfloat16 g_hh1hi[(size_t)MTOT*512];
__device__ __nv_bfloat16 g_hh1lo[(size_t)MTOT*512];
__device__ float g_g [MTOT*FOUTx];            // h@a12
__device__ float g_h2[MTOT*FOUTx];            // fa@W2
__device__ float g_Ax[MTOT];
__device__ float g_Ay[MTOT];
__device__ float g_e1[MTOT*8];
__device__ float g_e2[MTOT*8];
__device__ float g_S [(size_t)Bn*NN*NN];      // logits (134 MB)
__device__ __nv_bfloat16 g_Shi[(size_t)Bn*NN*NN];   // probs hi
__device__ __nv_bfloat16 g_Slo[(size_t)Bn*NN*NN];   // probs lo
__device__ __nv_bfloat16 g_Fhi[(size_t)Bn*FINx*NN]; // featT hi
__device__ __nv_bfloat16 g_Flo[(size_t)Bn*FINx*NN]; // featT lo
__device__ __nv_bfloat16 g_fRhi[(size_t)MTOT*FINx]; // feat row-major hi
__device__ __nv_bfloat16 g_fRlo[(size_t)MTOT*FINx];
__device__ __nv_bfloat16 g_fahi[(size_t)MTOT*FINx]; // fa hi
__device__ __nv_bfloat16 g_falo[(size_t)MTOT*FINx];
__device__ __nv_bfloat16 g_ghi[MTOT*FOUTx];   // g hi
__device__ __nv_bfloat16 g_glo[MTOT*FOUTx];
__device__ __nv_bfloat16 g_WW1th[512*FINx];   // [W^T ; W1^T] hi (512 rows x K=512)
__device__ __nv_bfloat16 g_WW1tl[512*FINx];
__device__ __nv_bfloat16 g_W2th[FOUTx*FINx];
__device__ __nv_bfloat16 g_W2tl[FOUTx*FINx];
__device__ __nv_bfloat16 g_a12th[FOUTx*FOUTx];
__device__ __nv_bfloat16 g_a12tl[FOUTx*FOUTx];
__device__ float g_fa[(size_t)MTOT*FINx];     // feat_agg

// ---------------- mma.sync / cp.async helpers (sm_80+) ----------------------
__device__ __forceinline__ uint32_t smem_u32(const void* p) {
    return (uint32_t)__cvta_generic_to_shared(p);
}
__device__ __forceinline__ void cp16(uint32_t s, const void* g) {
    asm volatile("cp.async.cg.shared.global [%0], [%1], 16;" :: "r"(s), "l"(g));
}
__device__ __forceinline__ void ldmx4(uint32_t* d, uint32_t a) {
    asm volatile("ldmatrix.sync.aligned.m8n8.x4.shared.b16 {%0,%1,%2,%3}, [%4];"
                 : "=r"(d[0]), "=r"(d[1]), "=r"(d[2]), "=r"(d[3]) : "r"(a));
}
__device__ __forceinline__ void mma_bf16(float* c, const uint32_t* a,
                                         uint32_t b0, uint32_t b1) {
    asm volatile("mma.sync.aligned.m16n8k16.row.col.f32.bf16.bf16.f32 "
                 "{%0,%1,%2,%3}, {%4,%5,%6,%7}, {%8,%9}, {%0,%1,%2,%3};"
                 : "+f"(c[0]), "+f"(c[1]), "+f"(c[2]), "+f"(c[3])
                 : "r"(a[0]), "r"(a[1]), "r"(a[2]), "r"(a[3]), "r"(b0), "r"(b1));
}
__device__ __forceinline__ float lrelu(float v) {
    return (v > 0.f) ? v : ALPHAc * v;
}
__device__ __forceinline__ float fast_exp(float x) {
    float t = x * 1.44269504088896f;
    t = fmaxf(t, -126.0f);
    const float n = rintf(t);
    const float f = t - n;
    float p = 1.5403530394e-4f;
    p = fmaf(p, f, 1.3333558146e-3f);
    p = fmaf(p, f, 9.6181291076e-3f);
    p = fmaf(p, f, 5.5504108664e-2f);
    p = fmaf(p, f, 2.4022650696e-1f);
    p = fmaf(p, f, 6.9314718056e-1f);
    p = fmaf(p, f, 1.0f);
    const int e = (int)n;
    return __int_as_float((e + 127) << 23) * p;
}
__device__ __forceinline__ void split_bf16(float v, __nv_bfloat16& h, __nv_bfloat16& l) {
    h = __float2bfloat16_rn(v);
    l = __float2bfloat16_rn(v - __bfloat162float(h));
}

// ---------------- HMMA GEMM: C = A @ B^T (bf16 3-pass split) ---------------
// CTA tile 128(M) x 128(N), 256 threads = 8 warps (4m x 2n), warp tile 32x64.
// A = [MA, lda] rows hi/lo (first K cols used), B = [NB, ldb] rows hi/lo.
// Batch via blockIdx.z (strides MA*lda / NB*ldb / MA*ldc).
// EPI==0: fp32 store. EPI==1: scores epilogue. EPI==2: fp32 + bf16 hi/lo split.
#define AGG_ROWB  80
#define AGG_ARR   10240
#define AGG_BUF   (4*AGG_ARR)
#define AGG_SMEM  (2*AGG_BUF)

template<int EPI>
__global__ void __launch_bounds__(256)
mma_gemm_k(const __nv_bfloat16* __restrict__ Ah, const __nv_bfloat16* __restrict__ Al,
           const __nv_bfloat16* __restrict__ Bh, const __nv_bfloat16* __restrict__ Bl,
           float* __restrict__ C, int K, int lda, int ldb, int MA, int NB, int ldc,
           const float* __restrict__ Ax, const float* __restrict__ Ay,
           const int* __restrict__ adj,
           __nv_bfloat16* __restrict__ Chi, __nv_bfloat16* __restrict__ Clo)
{
    extern __shared__ char smem[];
    const uint32_t sbase = smem_u32(smem);
    const int tid  = threadIdx.x;
    const int wid  = tid >> 5;
    const int lane = tid & 31;
    const int b  = blockIdx.z;
    const int m0 = blockIdx.y * 128;
    const int n0 = blockIdx.x * 128;

    const int r   = tid >> 2;
    const int seg = tid & 3;
    const __nv_bfloat16* gAh = Ah + ((size_t)b * MA + m0 + r) * lda + seg * 8;
    const __nv_bfloat16* gAl = Al + ((size_t)b * MA + m0 + r) * lda + seg * 8;
    const __nv_bfloat16* gBh = Bh + ((size_t)b * NB + n0 + r) * ldb + seg * 8;
    const __nv_bfloat16* gBl = Bl + ((size_t)b * NB + n0 + r) * ldb + seg * 8;
    const uint32_t sA = r * AGG_ROWB + seg * 16;
    const size_t gstepA = (size_t)64 * lda;
    const size_t gstepB = (size_t)64 * ldb;

    #define AGG_ISSUE(bufi, kc) do {                                           \
        const int kofs = (kc) * 32;                                            \
        uint32_t s0 = sbase + (bufi) * AGG_BUF + sA;                            \
        cp16(s0 + 0*AGG_ARR,               gAh + kofs);                         \
        cp16(s0 + 1*AGG_ARR,               gAl + kofs);                         \
        cp16(s0 + 2*AGG_ARR,               gBh + kofs);                         \
        cp16(s0 + 3*AGG_ARR,               gBl + kofs);                         \
        uint32_t s1 = s0 + 64 * AGG_ROWB;                                       \
        cp16(s1 + 0*AGG_ARR,               gAh + gstepA + kofs);                \
        cp16(s1 + 1*AGG_ARR,               gAl + gstepA + kofs);                \
        cp16(s1 + 2*AGG_ARR,               gBh + gstepB + kofs);                \
        cp16(s1 + 3*AGG_ARR,               gBl + gstepB + kofs);                \
        asm volatile("cp.async.commit_group;" ::: "memory");                    \
    } while (0)

    const int wm = wid & 3;
    const int wn = wid >> 2;

    float acc[2][8][4];
    #pragma unroll
    for (int mi = 0; mi < 2; mi++)
        #pragma unroll
        for (int nj = 0; nj < 8; nj++)
            #pragma unroll
            for (int q = 0; q < 4; q++) acc[mi][nj][q] = 0.f;

    const int NC = K / 32;
    AGG_ISSUE(0, 0);
    int buf = 0;
    for (int kc = 0; kc < NC; kc++) {
        if (kc + 1 < NC) {
            AGG_ISSUE(buf ^ 1, kc + 1);
            asm volatile("cp.async.wait_group 1;" ::: "memory");
        } else {
            asm volatile("cp.async.wait_group 0;" ::: "memory");
        }
        __syncthreads();

        const uint32_t base = sbase + buf * AGG_BUF;
        #pragma unroll
        for (int kq = 0; kq < 2; kq++) {
            const uint32_t aaddr = base
                + (uint32_t)((wm * 32 + (lane & 15)) * AGG_ROWB)
                + (uint32_t)((kq * 16 + (lane >> 4) * 8) * 2);
            uint32_t ah0[4], ah1[4], al0[4], al1[4];
            ldmx4(ah0, aaddr);
            ldmx4(ah1, aaddr + 16 * AGG_ROWB);
            ldmx4(al0, aaddr + 1*AGG_ARR);
            ldmx4(al1, aaddr + 1*AGG_ARR + 16 * AGG_ROWB);

            #pragma unroll
            for (int np = 0; np < 4; np++) {
                const uint32_t baddr = base + 2*AGG_ARR
                    + (uint32_t)((wn * 64 + np * 16 + (lane & 7) + ((lane >> 4) << 3)) * AGG_ROWB)
                    + (uint32_t)((kq * 16 + ((lane >> 3) & 1) * 8) * 2);
                uint32_t bh[4], bl[4];
                ldmx4(bh, baddr);
                ldmx4(bl, baddr + 1*AGG_ARR);
                const int j0 = np * 2, j1 = np * 2 + 1;
                mma_bf16(acc[0][j0], ah0, bh[0], bh[1]);
                mma_bf16(acc[0][j1], ah0, bh[2], bh[3]);
                mma_bf16(acc[1][j0], ah1, bh[0], bh[1]);
                mma_bf16(acc[1][j1], ah1, bh[2], bh[3]);
                mma_bf16(acc[0][j0], ah0, bl[0], bl[1]);
                mma_bf16(acc[0][j1], ah0, bl[2], bl[3]);
                mma_bf16(acc[1][j0], ah1, bl[0], bl[1]);
                mma_bf16(acc[1][j1], ah1, bl[2], bl[3]);
                mma_bf16(acc[0][j0], al0, bh[0], bh[1]);
                mma_bf16(acc[0][j1], al0, bh[2], bh[3]);
                mma_bf16(acc[1][j0], al1, bh[0], bh[1]);
                mma_bf16(acc[1][j1], al1, bh[2], bh[3]);
            }
        }
        __syncthreads();
        buf ^= 1;
    }
    #undef AGG_ISSUE

    // epilogue
    const int mbase = m0 + wm * 32;
    const int nbase = n0 + wn * 64;
    #pragma unroll
    for (int mi = 0; mi < 2; mi++) {
        #pragma unroll
        for (int nj = 0; nj < 8; nj++) {
            const int mm = mbase + mi * 16 + (lane >> 2);
            const int nc = nbase + nj * 8 + (lane & 3) * 2;
            const size_t i0 = ((size_t)b * MA + mm) * ldc + nc;
            float* d0 = C + i0;
            if (EPI == 0) {
                *(float2*)d0              = make_float2(acc[mi][nj][0], acc[mi][nj][1]);
                *(float2*)(d0 + 8 * ldc)  = make_float2(acc[mi][nj][2], acc[mi][nj][3]);
            } else if (EPI == 2) {
                const float2 v0 = make_float2(acc[mi][nj][0], acc[mi][nj][1]);
                const float2 v1 = make_float2(acc[mi][nj][2], acc[mi][nj][3]);
                *(float2*)d0              = v0;
                *(float2*)(d0 + 8 * ldc)  = v1;
                __nv_bfloat162 H0, L0, H1, L1;
                split_bf16(v0.x, H0.x, L0.x); split_bf16(v0.y, H0.y, L0.y);
                split_bf16(v1.x, H1.x, L1.x); split_bf16(v1.y, H1.y, L1.y);
                *(__nv_bfloat162*)(Chi + i0)            = H0;
                *(__nv_bfloat162*)(Clo + i0)            = L0;
                *(__nv_bfloat162*)(Chi + i0 + 8 * ldc)  = H1;
                *(__nv_bfloat162*)(Clo + i0 + 8 * ldc)  = L1;
            } else {
                const float2 axv = *(const float2*)(Ax + b * NN + nc);
                const float ay0 = Ay[b * NN + mm];
                const float ay1 = Ay[b * NN + mm + 8];
                float2 v0 = make_float2(lrelu(acc[mi][nj][0] + ay0 + axv.x),
                                        lrelu(acc[mi][nj][1] + ay0 + axv.y));
                float2 v1 = make_float2(lrelu(acc[mi][nj][2] + ay1 + axv.x),
                                        lrelu(acc[mi][nj][3] + ay1 + axv.y));
                const int* adp = adj + ((size_t)b * NN + mm) * NN + nc;
                int2 a0v = *(const int2*)adp;
                int2 a1v = *(const int2*)(adp + 8 * NN);
                v0.x = (a0v.x > 0) ? v0.x : NEGc;
                v0.y = (a0v.y > 0) ? v0.y : NEGc;
                v1.x = (a1v.x > 0) ? v1.x : NEGc;
                v1.y = (a1v.y > 0) ? v1.y : NEGc;
                *(float2*)d0             = v0;
                *(float2*)(d0 + 8 * ldc) = v1;
            }
        }
    }
}

// --------- generic transpose + split: dst[c][r] = split(src[r][c]) ----------
__global__ void tsplit_k(const float* __restrict__ src,
                         __nv_bfloat16* __restrict__ hi,
                         __nv_bfloat16* __restrict__ lo, int R, int C)
{
    __shared__ float t[32][33];
    const int r0 = blockIdx.y * 32;
    const int c0 = blockIdx.x * 32;
    const int tx = threadIdx.x, ty = threadIdx.y;   // (32, 8)
    #pragma unroll
    for (int i = 0; i < 4; i++)
        t[ty + 8*i][tx] = src[(size_t)(r0 + ty + 8*i) * C + c0 + tx];
    __syncthreads();
    #pragma unroll
    for (int i = 0; i < 4; i++) {
        const float v = t[tx][ty + 8*i];
        __nv_bfloat16 h, l;
        split_bf16(v, h, l);
        const size_t idx = (size_t)(c0 + ty + 8*i) * R + r0 + tx;
        hi[idx] = h;
        lo[idx] = l;
    }
}

// --------- batched transpose + split; also emits row-major split ------------
__global__ void transpose_split_k(const float* __restrict__ feat,
                                  __nv_bfloat16* __restrict__ Fhi,
                                  __nv_bfloat16* __restrict__ Flo,
                                  __nv_bfloat16* __restrict__ fRhi,
                                  __nv_bfloat16* __restrict__ fRlo)
{
    __shared__ float t[32][33];
    const int b  = blockIdx.z;
    const int n0 = blockIdx.x * 32;
    const int f0 = blockIdx.y * 32;
    const int tx = threadIdx.x, ty = threadIdx.y;   // (32, 8)

    #pragma unroll
    for (int i = 0; i < 4; i++) {
        const float v = feat[((size_t)b * NN + n0 + ty + 8*i) * FINx + f0 + tx];
        t[ty + 8*i][tx] = v;
        // row-major split (coalesced over tx)
        __nv_bfloat16 h, l;
        split_bf16(v, h, l);
        const size_t ridx = ((size_t)b * NN + n0 + ty + 8*i) * FINx + f0 + tx;
        fRhi[ridx] = h;
        fRlo[ridx] = l;
    }
    __syncthreads();
    #pragma unroll
    for (int i = 0; i < 4; i++) {
        const float v = t[tx][ty + 8*i];
        __nv_bfloat16 h, l;
        split_bf16(v, h, l);
        const size_t idx = ((size_t)b * FINx + f0 + ty + 8*i) * NN + n0 + tx;
        Fhi[idx] = h;
        Flo[idx] = l;
    }
}

// --------- Ax = h@a1, Ay = h@a2, e1[e] = feat row . L_w[e] (warp/row) -------
// h lives in fused hh1 buffer with row stride 512 (first 256 cols).
__global__ void small1_k(const float* __restrict__ hh1, const float* __restrict__ feat,
                         const float* __restrict__ a1, const float* __restrict__ a2,
                         const float* __restrict__ Lw,
                         float* __restrict__ Ax, float* __restrict__ Ay,
                         float* __restrict__ e1)
{
    const int warp = (blockIdx.x * blockDim.x + threadIdx.x) >> 5;
    const int lane = threadIdx.x & 31;
    if (warp >= MTOT) return;

    const float4* hr  = (const float4*)(hh1 + (size_t)warp * 512);
    const float4* a14 = (const float4*)a1;
    const float4* a24 = (const float4*)a2;
    float sx = 0.f, sy = 0.f;
    #pragma unroll
    for (int c = 0; c < 2; c++) {
        const float4 f = hr[lane + c * 32];
        const float4 u = a14[lane + c * 32];
        const float4 w = a24[lane + c * 32];
        sx += f.x*u.x + f.y*u.y + f.z*u.z + f.w*u.w;
        sy += f.x*w.x + f.y*w.y + f.z*w.z + f.w*w.w;
    }
    const float4* fr  = (const float4*)(feat + (size_t)warp * FINx);
    const float4* Lw4 = (const float4*)Lw;
    float acc[5] = {0.f, 0.f, 0.f, 0.f, 0.f};
    #pragma unroll
    for (int c = 0; c < 4; c++) {
        const float4 f = fr[lane + c * 32];
        #pragma unroll
        for (int e = 0; e < 5; e++) {
            const float4 w = Lw4[e * 128 + lane + c * 32];
            acc[e] += f.x*w.x + f.y*w.y + f.z*w.z + f.w*w.w;
        }
    }
    #pragma unroll
    for (int off = 16; off; off >>= 1) {
        sx += __shfl_xor_sync(0xffffffffu, sx, off);
        sy += __shfl_xor_sync(0xffffffffu, sy, off);
        #pragma unroll
        for (int e = 0; e < 5; e++) acc[e] += __shfl_xor_sync(0xffffffffu, acc[e], off);
    }
    if (lane == 0) {
        Ax[warp] = sx;
        Ay[warp] = sy;
        #pragma unroll
        for (int e = 0; e < 5; e++) e1[warp * 8 + e] = acc[e];
    }
}

// --------- e2[e] = feat_agg row . R_w[e] -----------------------------------
__global__ void small2_k(const float* __restrict__ fa, const float* __restrict__ Rw,
                         float* __restrict__ e2)
{
    const int warp = (blockIdx.x * blockDim.x + threadIdx.x) >> 5;
    const int lane = threadIdx.x & 31;
    if (warp >= MTOT) return;

    const float4* fr  = (const float4*)(fa + (size_t)warp * FINx);
    const float4* Rw4 = (const float4*)Rw;
    float acc[5] = {0.f, 0.f, 0.f, 0.f, 0.f};
    #pragma unroll
    for (int c = 0; c < 4; c++) {
        const float4 f = fr[lane + c * 32];
        #pragma unroll
        for (int e = 0; e < 5; e++) {
            const float4 w = Rw4[e * 128 + lane + c * 32];
            acc[e] += f.x*w.x + f.y*w.y + f.z*w.z + f.w*w.w;
        }
    }
    #pragma unroll
    for (int off = 16; off; off >>= 1) {
        #pragma unroll
        for (int e = 0; e < 5; e++) acc[e] += __shfl_xor_sync(0xffffffffu, acc[e], off);
    }
    if (lane == 0) {
        #pragma unroll
        for (int e = 0; e < 5; e++) e2[warp * 8 + e] = acc[e];
    }
}

// --------- row softmax over N=2048 -> bf16 hi/lo probs ----------------------
__global__ void __launch_bounds__(256)
softmax_k(const float* __restrict__ S,
          __nv_bfloat16* __restrict__ Phi, __nv_bfloat16* __restrict__ Plo)
{
    const float4* p4 = (const float4*)(S + (size_t)blockIdx.x * NN);
    const int t = threadIdx.x;
    float4 va = p4[t];
    float4 vb = p4[t + 256];
    float mx = fmaxf(fmaxf(fmaxf(va.x, va.y), fmaxf(va.z, va.w)),
                     fmaxf(fmaxf(vb.x, vb.y), fmaxf(vb.z, vb.w)));

    __shared__ float red[256];
    red[t] = mx; __syncthreads();
    #pragma unroll
    for (int s = 128; s > 0; s >>= 1) {
        if (t < s) red[t] = fmaxf(red[t], red[t + s]);
        __syncthreads();
    }
    mx = red[0];
    __syncthreads();

    va.x = fast_exp(va.x - mx); va.y = fast_exp(va.y - mx);
    va.z = fast_exp(va.z - mx); va.w = fast_exp(va.w - mx);
    vb.x = fast_exp(vb.x - mx); vb.y = fast_exp(vb.y - mx);
    vb.z = fast_exp(vb.z - mx); vb.w = fast_exp(vb.w - mx);
    float sum = (va.x + va.y) + (va.z + va.w) + (vb.x + vb.y) + (vb.z + vb.w);
    red[t] = sum; __syncthreads();
    #pragma unroll
    for (int s = 128; s > 0; s >>= 1) {
        if (t < s) red[t] += red[t + s];
        __syncthreads();
    }
    const float inv = 1.0f / red[0];

    __nv_bfloat16* ph = Phi + (size_t)blockIdx.x * NN;
    __nv_bfloat16* pl = Plo + (size_t)blockIdx.x * NN;
    __nv_bfloat162 H[2], L[2];
    split_bf16(va.x * inv, H[0].x, L[0].x); split_bf16(va.y * inv, H[0].y, L[0].y);
    split_bf16(va.z * inv, H[1].x, L[1].x); split_bf16(va.w * inv, H[1].y, L[1].y);
    *(uint2*)(ph + t * 4) = *(uint2*)H;
    *(uint2*)(pl + t * 4) = *(uint2*)L;
    split_bf16(vb.x * inv, H[0].x, L[0].x); split_bf16(vb.y * inv, H[0].y, L[0].y);
    split_bf16(vb.z * inv, H[1].x, L[1].x); split_bf16(vb.w * inv, H[1].y, L[1].y);
    *(uint2*)(ph + 1024 + t * 4) = *(uint2*)H;
    *(uint2*)(pl + 1024 + t * 4) = *(uint2*)L;
}

// --------- out = h1 + h2 + e1^T B_w[o] e2  (h1 strided in hh1) --------------
__global__ void __launch_bounds__(256)
final_k(const float* __restrict__ hh1, const float* __restrict__ h2,
        const float* __restrict__ e1, const float* __restrict__ e2,
        const float* __restrict__ Bw, float* __restrict__ out)
{
    const int m = blockIdx.x;
    const int o = threadIdx.x;   // 0..255
    __shared__ float s1[8], s2[8];
    if (o < 5) { s1[o] = e1[m * 8 + o]; s2[o] = e2[m * 8 + o]; }
    __syncthreads();

    const float* bw = Bw + o * 25;
    float s = 0.f;
    #pragma unroll
    for (int i = 0; i < 5; i++) {
        const float ei = s1[i];
        #pragma unroll
        for (int j = 0; j < 5; j++) s += ei * bw[i * 5 + j] * s2[j];
    }
    out[(size_t)m * FOUTx + o] = hh1[(size_t)m * 512 + 256 + o]
                               + h2[(size_t)m * FOUTx + o] + s;
}

// ---------------------------------------------------------------------------
extern "C" void kernel_launch(void* const* d_in, const int* in_sizes, int n_in,
                              void* d_out, int out_size)
{
    const float* feat = (const float*)d_in[0];
    const int*   adj  = (const int*)  d_in[1];
    const float* W    = (const float*)d_in[2];
    const float* W1   = (const float*)d_in[3];
    const float* W2   = (const float*)d_in[4];
    const float* a1   = (const float*)d_in[5];
    const float* a2   = (const float*)d_in[6];
    const float* a12  = (const float*)d_in[7];
    const float* Lw   = (const float*)d_in[8];
    const float* Rw   = (const float*)d_in[9];
    const float* Bw   = (const float*)d_in[10];
    float* out = (float*)d_out;

    float *hh1, *g, *h2, *Ax, *Ay, *e1, *e2, *S, *fa;
    __nv_bfloat16 *hh1hi, *hh1lo, *Shi, *Slo, *Fhi, *Flo, *ghi, *glo;
    __nv_bfloat16 *fRhi, *fRlo, *fahi, *falo;
    __nv_bfloat16 *WW1th, *WW1tl, *W2th, *W2tl, *a12th, *a12tl;
    cudaGetSymbolAddress((void**)&hh1,   g_hh1);
    cudaGetSymbolAddress((void**)&hh1hi, g_hh1hi);
    cudaGetSymbolAddress((void**)&hh1lo, g_hh1lo);
    cudaGetSymbolAddress((void**)&g,  g_g);
    cudaGetSymbolAddress((void**)&h2, g_h2);
    cudaGetSymbolAddress((void**)&Ax, g_Ax);
    cudaGetSymbolAddress((void**)&Ay, g_Ay);
    cudaGetSymbolAddress((void**)&e1, g_e1);
    cudaGetSymbolAddress((void**)&e2, g_e2);
    cudaGetSymbolAddress((void**)&S,  g_S);
    cudaGetSymbolAddress((void**)&fa, g_fa);
    cudaGetSymbolAddress((void**)&Shi, g_Shi);
    cudaGetSymbolAddress((void**)&Slo, g_Slo);
    cudaGetSymbolAddress((void**)&Fhi, g_Fhi);
    cudaGetSymbolAddress((void**)&Flo, g_Flo);
    cudaGetSymbolAddress((void**)&ghi, g_ghi);
    cudaGetSymbolAddress((void**)&glo, g_glo);
    cudaGetSymbolAddress((void**)&fRhi, g_fRhi);
    cudaGetSymbolAddress((void**)&fRlo, g_fRlo);
    cudaGetSymbolAddress((void**)&fahi, g_fahi);
    cudaGetSymbolAddress((void**)&falo, g_falo);
    cudaGetSymbolAddress((void**)&WW1th, g_WW1th);
    cudaGetSymbolAddress((void**)&WW1tl, g_WW1tl);
    cudaGetSymbolAddress((void**)&W2th, g_W2th);
    cudaGetSymbolAddress((void**)&W2tl, g_W2tl);
    cudaGetSymbolAddress((void**)&a12th, g_a12th);
    cudaGetSymbolAddress((void**)&a12tl, g_a12tl);

    static int smem_set = 0;
    if (!smem_set) {
        cudaFuncSetAttribute(mma_gemm_k<0>, cudaFuncAttributeMaxDynamicSharedMemorySize,
                             AGG_SMEM);
        cudaFuncSetAttribute(mma_gemm_k<1>, cudaFuncAttributeMaxDynamicSharedMemorySize,
                             AGG_SMEM);
        cudaFuncSetAttribute(mma_gemm_k<2>, cudaFuncAttributeMaxDynamicSharedMemorySize,
                             AGG_SMEM);
        smem_set = 1;
    }

    const dim3 blk(256);
    const dim3 tb(32, 8);

    // weight transposes + splits (tiny); [W^T ; W1^T] fused into one buffer
    tsplit_k<<<dim3(FOUTx/32, FINx/32), tb>>>(W,  WW1th,             WW1tl,             FINx, FOUTx);
    tsplit_k<<<dim3(FOUTx/32, FINx/32), tb>>>(W1, WW1th + 256*FINx,  WW1tl + 256*FINx,  FINx, FOUTx);
    tsplit_k<<<dim3(FOUTx/32, FINx/32), tb>>>(W2, W2th, W2tl, FINx, FOUTx);
    tsplit_k<<<dim3(FOUTx/32, FOUTx/32), tb>>>(a12, a12th, a12tl, FOUTx, FOUTx);

    // feat: transposed split (B of agg) + row-major split (A operand), one kernel
    transpose_split_k<<<dim3(NN/32, FINx/32, Bn), tb>>>(feat, Fhi, Flo, fRhi, fRlo);

    // [h | h1] = feat @ [W | W1]  (one HMMA GEMM, NB=512, fused hi/lo split)
    mma_gemm_k<2><<<dim3(512/128, MTOT/128, 1), blk, AGG_SMEM>>>(
        fRhi, fRlo, WW1th, WW1tl, hh1, FINx, FINx, FINx, MTOT, 512, 512,
        nullptr, nullptr, nullptr, hh1hi, hh1lo);

    // Ax, Ay, e1
    small1_k<<<MTOT/8, 256>>>(hh1, feat, a1, a2, Lw, Ax, Ay, e1);

    // g = h @ a12  (A = h half of hh1hi, lda=512; fused hi/lo split)
    mma_gemm_k<2><<<dim3(FOUTx/128, MTOT/128, 1), blk, AGG_SMEM>>>(
        hh1hi, hh1lo, a12th, a12tl, g, FOUTx, 512, FOUTx, MTOT, FOUTx, FOUTx,
        nullptr, nullptr, nullptr, ghi, glo);

    // S = leaky(Ax+Ay+g.h^T) masked  (B = h half of hh1hi, ldb=512)
    mma_gemm_k<1><<<dim3(NN/128, NN/128, Bn), blk, AGG_SMEM>>>(
        ghi, glo, hh1hi, hh1lo, S, FOUTx, FOUTx, 512, NN, NN, NN,
        Ax, Ay, adj, nullptr, nullptr);

    // row softmax -> bf16 hi/lo probs
    softmax_k<<<MTOT, 256>>>(S, Shi, Slo);

    // feat_agg = P @ feat  (fused hi/lo split)
    mma_gemm_k<2><<<dim3(FINx/128, NN/128, Bn), blk, AGG_SMEM>>>(
        Shi, Slo, Fhi, Flo, fa, NN, NN, NN, NN, FINx, FINx,
        nullptr, nullptr, nullptr, fahi, falo);

    // h2 = fa @ W2 ; e2
    mma_gemm_k<0><<<dim3(FOUTx/128, MTOT/128, 1), blk, AGG_SMEM>>>(
        fahi, falo, W2th, W2tl, h2, FINx, FINx, FINx, MTOT, FOUTx, FOUTx,
        nullptr, nullptr, nullptr, nullptr, nullptr);
    small2_k<<<MTOT/8, 256>>>(fa, Rw, e2);

    // out = h1 + h2 + bilinear(e1, B_w, e2)
    final_k<<<MTOT, 256>>>(hh1, h2, e1, e2, Bw, out);
}

// round 15
// speedup vs baseline: 1.0180x; 1.0156x over previous
#include <cuda_runtime.h>
#include <cuda_bf16.h>
#include <cstdint>

// Problem constants
#define Bn    8
#define NN    2048
#define FINx  512
#define FOUTx 256
#define MTOT  (Bn*NN)          // 16384
#define ALPHAc 0.2f
#define NEGc  (-9e15f)

// ---------------- scratch (device globals: allocation-free) ----------------
__device__ __nv_bfloat16 g_hh1hi[(size_t)MTOT*512];  // [h | h1] hi (ld 512)
__device__ __nv_bfloat16 g_hh1lo[(size_t)MTOT*512];
__device__ float g_h2[MTOT*FOUTx];            // fa@W2
__device__ float g_Ax[MTOT];
__device__ float g_Ay[MTOT];
__device__ float g_e1[MTOT*8];
__device__ float g_e2[MTOT*8];
__device__ float g_S [(size_t)Bn*NN*NN];      // logits (134 MB)
__device__ __nv_bfloat16 g_Shi[(size_t)Bn*NN*NN];   // probs hi
__device__ __nv_bfloat16 g_Slo[(size_t)Bn*NN*NN];   // probs lo
__device__ __nv_bfloat16 g_Fhi[(size_t)Bn*FINx*NN]; // featT hi
__device__ __nv_bfloat16 g_Flo[(size_t)Bn*FINx*NN]; // featT lo
__device__ __nv_bfloat16 g_fRhi[(size_t)MTOT*FINx]; // feat row-major hi
__device__ __nv_bfloat16 g_fRlo[(size_t)MTOT*FINx];
__device__ __nv_bfloat16 g_fahi[(size_t)MTOT*FINx]; // fa hi
__device__ __nv_bfloat16 g_falo[(size_t)MTOT*FINx];
__device__ __nv_bfloat16 g_ghi[MTOT*FOUTx];   // g hi
__device__ __nv_bfloat16 g_glo[MTOT*FOUTx];
__device__ __nv_bfloat16 g_WW1th[512*FINx];   // [W^T ; W1^T] hi
__device__ __nv_bfloat16 g_WW1tl[512*FINx];
__device__ __nv_bfloat16 g_W2th[FOUTx*FINx];
__device__ __nv_bfloat16 g_W2tl[FOUTx*FINx];
__device__ __nv_bfloat16 g_a12th[FOUTx*FOUTx];
__device__ __nv_bfloat16 g_a12tl[FOUTx*FOUTx];

// ---------------- mma.sync / cp.async helpers (sm_80+) ----------------------
__device__ __forceinline__ uint32_t smem_u32(const void* p) {
    return (uint32_t)__cvta_generic_to_shared(p);
}
__device__ __forceinline__ void cp16(uint32_t s, const void* g) {
    asm volatile("cp.async.cg.shared.global [%0], [%1], 16;" :: "r"(s), "l"(g));
}
__device__ __forceinline__ void ldmx4(uint32_t* d, uint32_t a) {
    asm volatile("ldmatrix.sync.aligned.m8n8.x4.shared.b16 {%0,%1,%2,%3}, [%4];"
                 : "=r"(d[0]), "=r"(d[1]), "=r"(d[2]), "=r"(d[3]) : "r"(a));
}
__device__ __forceinline__ void mma_bf16(float* c, const uint32_t* a,
                                         uint32_t b0, uint32_t b1) {
    asm volatile("mma.sync.aligned.m16n8k16.row.col.f32.bf16.bf16.f32 "
                 "{%0,%1,%2,%3}, {%4,%5,%6,%7}, {%8,%9}, {%0,%1,%2,%3};"
                 : "+f"(c[0]), "+f"(c[1]), "+f"(c[2]), "+f"(c[3])
                 : "r"(a[0]), "r"(a[1]), "r"(a[2]), "r"(a[3]), "r"(b0), "r"(b1));
}
__device__ __forceinline__ float lrelu(float v) {
    return (v > 0.f) ? v : ALPHAc * v;
}
__device__ __forceinline__ float fast_exp(float x) {
    float t = x * 1.44269504088896f;
    t = fmaxf(t, -126.0f);
    const float n = rintf(t);
    const float f = t - n;
    float p = 1.5403530394e-4f;
    p = fmaf(p, f, 1.3333558146e-3f);
    p = fmaf(p, f, 9.6181291076e-3f);
    p = fmaf(p, f, 5.5504108664e-2f);
    p = fmaf(p, f, 2.4022650696e-1f);
    p = fmaf(p, f, 6.9314718056e-1f);
    p = fmaf(p, f, 1.0f);
    const int e = (int)n;
    return __int_as_float((e + 127) << 23) * p;
}
__device__ __forceinline__ void split_bf16(float v, __nv_bfloat16& h, __nv_bfloat16& l) {
    h = __float2bfloat16_rn(v);
    l = __float2bfloat16_rn(v - __bfloat162float(h));
}

// ---------------- HMMA GEMM: C = A @ B^T (bf16 3-pass split) ---------------
// EPI==0: fp32. EPI==1: scores epilogue. EPI==2: fp32 + hi/lo. EPI==3: hi/lo only.
#define AGG_ROWB  80
#define AGG_ARR   10240
#define AGG_BUF   (4*AGG_ARR)
#define AGG_SMEM  (2*AGG_BUF)

template<int EPI>
__global__ void __launch_bounds__(256)
mma_gemm_k(const __nv_bfloat16* __restrict__ Ah, const __nv_bfloat16* __restrict__ Al,
           const __nv_bfloat16* __restrict__ Bh, const __nv_bfloat16* __restrict__ Bl,
           float* __restrict__ C, int K, int lda, int ldb, int MA, int NB, int ldc,
           const float* __restrict__ Ax, const float* __restrict__ Ay,
           const int* __restrict__ adj,
           __nv_bfloat16* __restrict__ Chi, __nv_bfloat16* __restrict__ Clo)
{
    extern __shared__ char smem[];
    const uint32_t sbase = smem_u32(smem);
    const int tid  = threadIdx.x;
    const int wid  = tid >> 5;
    const int lane = tid & 31;
    const int b  = blockIdx.z;
    const int m0 = blockIdx.y * 128;
    const int n0 = blockIdx.x * 128;

    const int r   = tid >> 2;
    const int seg = tid & 3;
    const __nv_bfloat16* gAh = Ah + ((size_t)b * MA + m0 + r) * lda + seg * 8;
    const __nv_bfloat16* gAl = Al + ((size_t)b * MA + m0 + r) * lda + seg * 8;
    const __nv_bfloat16* gBh = Bh + ((size_t)b * NB + n0 + r) * ldb + seg * 8;
    const __nv_bfloat16* gBl = Bl + ((size_t)b * NB + n0 + r) * ldb + seg * 8;
    const uint32_t sA = r * AGG_ROWB + seg * 16;
    const size_t gstepA = (size_t)64 * lda;
    const size_t gstepB = (size_t)64 * ldb;

    #define AGG_ISSUE(bufi, kc) do {                                           \
        const int kofs = (kc) * 32;                                            \
        uint32_t s0 = sbase + (bufi) * AGG_BUF + sA;                            \
        cp16(s0 + 0*AGG_ARR,               gAh + kofs);                         \
        cp16(s0 + 1*AGG_ARR,               gAl + kofs);                         \
        cp16(s0 + 2*AGG_ARR,               gBh + kofs);                         \
        cp16(s0 + 3*AGG_ARR,               gBl + kofs);                         \
        uint32_t s1 = s0 + 64 * AGG_ROWB;                                       \
        cp16(s1 + 0*AGG_ARR,               gAh + gstepA + kofs);                \
        cp16(s1 + 1*AGG_ARR,               gAl + gstepA + kofs);                \
        cp16(s1 + 2*AGG_ARR,               gBh + gstepB + kofs);                \
        cp16(s1 + 3*AGG_ARR,               gBl + gstepB + kofs);                \
        asm volatile("cp.async.commit_group;" ::: "memory");                    \
    } while (0)

    const int wm = wid & 3;
    const int wn = wid >> 2;

    float acc[2][8][4];
    #pragma unroll
    for (int mi = 0; mi < 2; mi++)
        #pragma unroll
        for (int nj = 0; nj < 8; nj++)
            #pragma unroll
            for (int q = 0; q < 4; q++) acc[mi][nj][q] = 0.f;

    const int NC = K / 32;
    AGG_ISSUE(0, 0);
    int buf = 0;
    for (int kc = 0; kc < NC; kc++) {
        if (kc + 1 < NC) {
            AGG_ISSUE(buf ^ 1, kc + 1);
            asm volatile("cp.async.wait_group 1;" ::: "memory");
        } else {
            asm volatile("cp.async.wait_group 0;" ::: "memory");
        }
        __syncthreads();

        const uint32_t base = sbase + buf * AGG_BUF;
        #pragma unroll
        for (int kq = 0; kq < 2; kq++) {
            const uint32_t aaddr = base
                + (uint32_t)((wm * 32 + (lane & 15)) * AGG_ROWB)
                + (uint32_t)((kq * 16 + (lane >> 4) * 8) * 2);
            uint32_t ah0[4], ah1[4], al0[4], al1[4];
            ldmx4(ah0, aaddr);
            ldmx4(ah1, aaddr + 16 * AGG_ROWB);
            ldmx4(al0, aaddr + 1*AGG_ARR);
            ldmx4(al1, aaddr + 1*AGG_ARR + 16 * AGG_ROWB);

            #pragma unroll
            for (int np = 0; np < 4; np++) {
                const uint32_t baddr = base + 2*AGG_ARR
                    + (uint32_t)((wn * 64 + np * 16 + (lane & 7) + ((lane >> 4) << 3)) * AGG_ROWB)
                    + (uint32_t)((kq * 16 + ((lane >> 3) & 1) * 8) * 2);
                uint32_t bh[4], bl[4];
                ldmx4(bh, baddr);
                ldmx4(bl, baddr + 1*AGG_ARR);
                const int j0 = np * 2, j1 = np * 2 + 1;
                mma_bf16(acc[0][j0], ah0, bh[0], bh[1]);
                mma_bf16(acc[0][j1], ah0, bh[2], bh[3]);
                mma_bf16(acc[1][j0], ah1, bh[0], bh[1]);
                mma_bf16(acc[1][j1], ah1, bh[2], bh[3]);
                mma_bf16(acc[0][j0], ah0, bl[0], bl[1]);
                mma_bf16(acc[0][j1], ah0, bl[2], bl[3]);
                mma_bf16(acc[1][j0], ah1, bl[0], bl[1]);
                mma_bf16(acc[1][j1], ah1, bl[2], bl[3]);
                mma_bf16(acc[0][j0], al0, bh[0], bh[1]);
                mma_bf16(acc[0][j1], al0, bh[2], bh[3]);
                mma_bf16(acc[1][j0], al1, bh[0], bh[1]);
                mma_bf16(acc[1][j1], al1, bh[2], bh[3]);
            }
        }
        __syncthreads();
        buf ^= 1;
    }
    #undef AGG_ISSUE

    // epilogue
    const int mbase = m0 + wm * 32;
    const int nbase = n0 + wn * 64;
    #pragma unroll
    for (int mi = 0; mi < 2; mi++) {
        #pragma unroll
        for (int nj = 0; nj < 8; nj++) {
            const int mm = mbase + mi * 16 + (lane >> 2);
            const int nc = nbase + nj * 8 + (lane & 3) * 2;
            const size_t i0 = ((size_t)b * MA + mm) * ldc + nc;
            if (EPI == 0) {
                float* d0 = C + i0;
                *(float2*)d0              = make_float2(acc[mi][nj][0], acc[mi][nj][1]);
                *(float2*)(d0 + 8 * ldc)  = make_float2(acc[mi][nj][2], acc[mi][nj][3]);
            } else if (EPI == 2 || EPI == 3) {
                const float2 v0 = make_float2(acc[mi][nj][0], acc[mi][nj][1]);
                const float2 v1 = make_float2(acc[mi][nj][2], acc[mi][nj][3]);
                if (EPI == 2) {
                    float* d0 = C + i0;
                    *(float2*)d0              = v0;
                    *(float2*)(d0 + 8 * ldc)  = v1;
                }
                __nv_bfloat162 H0, L0, H1, L1;
                split_bf16(v0.x, H0.x, L0.x); split_bf16(v0.y, H0.y, L0.y);
                split_bf16(v1.x, H1.x, L1.x); split_bf16(v1.y, H1.y, L1.y);
                *(__nv_bfloat162*)(Chi + i0)            = H0;
                *(__nv_bfloat162*)(Clo + i0)            = L0;
                *(__nv_bfloat162*)(Chi + i0 + 8 * ldc)  = H1;
                *(__nv_bfloat162*)(Clo + i0 + 8 * ldc)  = L1;
            } else {
                float* d0 = C + i0;
                const float2 axv = *(const float2*)(Ax + b * NN + nc);
                const float ay0 = Ay[b * NN + mm];
                const float ay1 = Ay[b * NN + mm + 8];
                float2 v0 = make_float2(lrelu(acc[mi][nj][0] + ay0 + axv.x),
                                        lrelu(acc[mi][nj][1] + ay0 + axv.y));
                float2 v1 = make_float2(lrelu(acc[mi][nj][2] + ay1 + axv.x),
                                        lrelu(acc[mi][nj][3] + ay1 + axv.y));
                const int* adp = adj + ((size_t)b * NN + mm) * NN + nc;
                int2 a0v = *(const int2*)adp;
                int2 a1v = *(const int2*)(adp + 8 * NN);
                v0.x = (a0v.x > 0) ? v0.x : NEGc;
                v0.y = (a0v.y > 0) ? v0.y : NEGc;
                v1.x = (a1v.x > 0) ? v1.x : NEGc;
                v1.y = (a1v.y > 0) ? v1.y : NEGc;
                *(float2*)d0             = v0;
                *(float2*)(d0 + 8 * ldc) = v1;
            }
        }
    }
}

// --------- generic transpose + split: dst[c][r] = split(src[r][c]) ----------
__global__ void tsplit_k(const float* __restrict__ src,
                         __nv_bfloat16* __restrict__ hi,
                         __nv_bfloat16* __restrict__ lo, int R, int C)
{
    __shared__ float t[32][33];
    const int r0 = blockIdx.y * 32;
    const int c0 = blockIdx.x * 32;
    const int tx = threadIdx.x, ty = threadIdx.y;   // (32, 8)
    #pragma unroll
    for (int i = 0; i < 4; i++)
        t[ty + 8*i][tx] = src[(size_t)(r0 + ty + 8*i) * C + c0 + tx];
    __syncthreads();
    #pragma unroll
    for (int i = 0; i < 4; i++) {
        const float v = t[tx][ty + 8*i];
        __nv_bfloat16 h, l;
        split_bf16(v, h, l);
        const size_t idx = (size_t)(c0 + ty + 8*i) * R + r0 + tx;
        hi[idx] = h;
        lo[idx] = l;
    }
}

// --------- batched transpose + split; also emits row-major split ------------
__global__ void transpose_split_k(const float* __restrict__ feat,
                                  __nv_bfloat16* __restrict__ Fhi,
                                  __nv_bfloat16* __restrict__ Flo,
                                  __nv_bfloat16* __restrict__ fRhi,
                                  __nv_bfloat16* __restrict__ fRlo)
{
    __shared__ float t[32][33];
    const int b  = blockIdx.z;
    const int n0 = blockIdx.x * 32;
    const int f0 = blockIdx.y * 32;
    const int tx = threadIdx.x, ty = threadIdx.y;   // (32, 8)

    #pragma unroll
    for (int i = 0; i < 4; i++) {
        const float v = feat[((size_t)b * NN + n0 + ty + 8*i) * FINx + f0 + tx];
        t[ty + 8*i][tx] = v;
        __nv_bfloat16 h, l;
        split_bf16(v, h, l);
        const size_t ridx = ((size_t)b * NN + n0 + ty + 8*i) * FINx + f0 + tx;
        fRhi[ridx] = h;
        fRlo[ridx] = l;
    }
    __syncthreads();
    #pragma unroll
    for (int i = 0; i < 4; i++) {
        const float v = t[tx][ty + 8*i];
        __nv_bfloat16 h, l;
        split_bf16(v, h, l);
        const size_t idx = ((size_t)b * FINx + f0 + ty + 8*i) * NN + n0 + tx;
        Fhi[idx] = h;
        Flo[idx] = l;
    }
}

// --------- Ax = h@a1, Ay = h@a2, e1[e] = feat row . L_w[e] (warp/row) -------
// h reconstructed from hh1hi+hh1lo (row stride 512, first 256 cols).
__global__ void small1_k(const __nv_bfloat16* __restrict__ hhi,
                         const __nv_bfloat16* __restrict__ hlo,
                         const float* __restrict__ feat,
                         const float* __restrict__ a1, const float* __restrict__ a2,
                         const float* __restrict__ Lw,
                         float* __restrict__ Ax, float* __restrict__ Ay,
                         float* __restrict__ e1)
{
    const int warp = (blockIdx.x * blockDim.x + threadIdx.x) >> 5;
    const int lane = threadIdx.x & 31;
    if (warp >= MTOT) return;

    // h: 8 bf16-pairs per lane (256 cols total)
    const uint4 uh = *(const uint4*)(hhi + (size_t)warp * 512 + lane * 8);
    const uint4 ul = *(const uint4*)(hlo + (size_t)warp * 512 + lane * 8);
    const __nv_bfloat162* hp = (const __nv_bfloat162*)&uh;
    const __nv_bfloat162* lp = (const __nv_bfloat162*)&ul;
    float hv[8];
    #pragma unroll
    for (int i = 0; i < 4; i++) {
        const float2 a = __bfloat1622float2(hp[i]);
        const float2 bb = __bfloat1622float2(lp[i]);
        hv[2*i]   = a.x + bb.x;
        hv[2*i+1] = a.y + bb.y;
    }
    const float4* a14 = (const float4*)a1;
    const float4* a24 = (const float4*)a2;
    const float4 u0 = a14[lane*2], u1 = a14[lane*2+1];
    const float4 w0 = a24[lane*2], w1 = a24[lane*2+1];
    float sx = hv[0]*u0.x + hv[1]*u0.y + hv[2]*u0.z + hv[3]*u0.w
             + hv[4]*u1.x + hv[5]*u1.y + hv[6]*u1.z + hv[7]*u1.w;
    float sy = hv[0]*w0.x + hv[1]*w0.y + hv[2]*w0.z + hv[3]*w0.w
             + hv[4]*w1.x + hv[5]*w1.y + hv[6]*w1.z + hv[7]*w1.w;

    const float4* fr  = (const float4*)(feat + (size_t)warp * FINx);
    const float4* Lw4 = (const float4*)Lw;
    float acc[5] = {0.f, 0.f, 0.f, 0.f, 0.f};
    #pragma unroll
    for (int c = 0; c < 4; c++) {
        const float4 f = fr[lane + c * 32];
        #pragma unroll
        for (int e = 0; e < 5; e++) {
            const float4 w = Lw4[e * 128 + lane + c * 32];
            acc[e] += f.x*w.x + f.y*w.y + f.z*w.z + f.w*w.w;
        }
    }
    #pragma unroll
    for (int off = 16; off; off >>= 1) {
        sx += __shfl_xor_sync(0xffffffffu, sx, off);
        sy += __shfl_xor_sync(0xffffffffu, sy, off);
        #pragma unroll
        for (int e = 0; e < 5; e++) acc[e] += __shfl_xor_sync(0xffffffffu, acc[e], off);
    }
    if (lane == 0) {
        Ax[warp] = sx;
        Ay[warp] = sy;
        #pragma unroll
        for (int e = 0; e < 5; e++) e1[warp * 8 + e] = acc[e];
    }
}

// --------- e2[e] = fa row . R_w[e]; fa from fahi+falo -----------------------
__global__ void small2_k(const __nv_bfloat16* __restrict__ fhi,
                         const __nv_bfloat16* __restrict__ flo,
                         const float* __restrict__ Rw, float* __restrict__ e2)
{
    const int warp = (blockIdx.x * blockDim.x + threadIdx.x) >> 5;
    const int lane = threadIdx.x & 31;
    if (warp >= MTOT) return;

    const uint4* fh = (const uint4*)(fhi + (size_t)warp * FINx);
    const uint4* fl = (const uint4*)(flo + (size_t)warp * FINx);
    const float4* Rw4 = (const float4*)Rw;
    float acc[5] = {0.f, 0.f, 0.f, 0.f, 0.f};
    #pragma unroll
    for (int c = 0; c < 2; c++) {
        const uint4 uh = fh[lane + c * 32];
        const uint4 ul = fl[lane + c * 32];
        const __nv_bfloat162* hp = (const __nv_bfloat162*)&uh;
        const __nv_bfloat162* lp = (const __nv_bfloat162*)&ul;
        float v[8];
        #pragma unroll
        for (int i = 0; i < 4; i++) {
            const float2 a = __bfloat1622float2(hp[i]);
            const float2 bb = __bfloat1622float2(lp[i]);
            v[2*i]   = a.x + bb.x;
            v[2*i+1] = a.y + bb.y;
        }
        const int f4 = (lane + c * 32) * 2;   // float4 index of first 4 cols
        #pragma unroll
        for (int e = 0; e < 5; e++) {
            const float4 w0 = Rw4[e * 128 + f4];
            const float4 w1 = Rw4[e * 128 + f4 + 1];
            acc[e] += v[0]*w0.x + v[1]*w0.y + v[2]*w0.z + v[3]*w0.w
                    + v[4]*w1.x + v[5]*w1.y + v[6]*w1.z + v[7]*w1.w;
        }
    }
    #pragma unroll
    for (int off = 16; off; off >>= 1) {
        #pragma unroll
        for (int e = 0; e < 5; e++) acc[e] += __shfl_xor_sync(0xffffffffu, acc[e], off);
    }
    if (lane == 0) {
        #pragma unroll
        for (int e = 0; e < 5; e++) e2[warp * 8 + e] = acc[e];
    }
}

// --------- row softmax over N=2048 -> bf16 hi/lo probs (2 barriers) ---------
__global__ void __launch_bounds__(256)
softmax_k(const float* __restrict__ S,
          __nv_bfloat16* __restrict__ Phi, __nv_bfloat16* __restrict__ Plo)
{
    const float4* p4 = (const float4*)(S + (size_t)blockIdx.x * NN);
    const int t = threadIdx.x;
    const int w = t >> 5, ln = t & 31;
    float4 va = p4[t];
    float4 vb = p4[t + 256];
    float mx = fmaxf(fmaxf(fmaxf(va.x, va.y), fmaxf(va.z, va.w)),
                     fmaxf(fmaxf(vb.x, vb.y), fmaxf(vb.z, vb.w)));
    #pragma unroll
    for (int o = 16; o; o >>= 1) mx = fmaxf(mx, __shfl_xor_sync(0xffffffffu, mx, o));

    __shared__ float sm[8], ss[8];
    if (ln == 0) sm[w] = mx;
    __syncthreads();
    mx = fmaxf(fmaxf(fmaxf(sm[0], sm[1]), fmaxf(sm[2], sm[3])),
               fmaxf(fmaxf(sm[4], sm[5]), fmaxf(sm[6], sm[7])));

    va.x = fast_exp(va.x - mx); va.y = fast_exp(va.y - mx);
    va.z = fast_exp(va.z - mx); va.w = fast_exp(va.w - mx);
    vb.x = fast_exp(vb.x - mx); vb.y = fast_exp(vb.y - mx);
    vb.z = fast_exp(vb.z - mx); vb.w = fast_exp(vb.w - mx);
    float sum = (va.x + va.y) + (va.z + va.w) + (vb.x + vb.y) + (vb.z + vb.w);
    #pragma unroll
    for (int o = 16; o; o >>= 1) sum += __shfl_xor_sync(0xffffffffu, sum, o);
    if (ln == 0) ss[w] = sum;
    __syncthreads();
    sum = ((ss[0] + ss[1]) + (ss[2] + ss[3])) + ((ss[4] + ss[5]) + (ss[6] + ss[7]));
    const float inv = 1.0f / sum;

    __nv_bfloat16* ph = Phi + (size_t)blockIdx.x * NN;
    __nv_bfloat16* pl = Plo + (size_t)blockIdx.x * NN;
    __nv_bfloat162 H[2], L[2];
    split_bf16(va.x * inv, H[0].x, L[0].x); split_bf16(va.y * inv, H[0].y, L[0].y);
    split_bf16(va.z * inv, H[1].x, L[1].x); split_bf16(va.w * inv, H[1].y, L[1].y);
    *(uint2*)(ph + t * 4) = *(uint2*)H;
    *(uint2*)(pl + t * 4) = *(uint2*)L;
    split_bf16(vb.x * inv, H[0].x, L[0].x); split_bf16(vb.y * inv, H[0].y, L[0].y);
    split_bf16(vb.z * inv, H[1].x, L[1].x); split_bf16(vb.w * inv, H[1].y, L[1].y);
    *(uint2*)(ph + 1024 + t * 4) = *(uint2*)H;
    *(uint2*)(pl + 1024 + t * 4) = *(uint2*)L;
}

// --------- out = h1 + h2 + e1^T B_w[o] e2  (h1 from hh1hi/lo) ---------------
__global__ void __launch_bounds__(256)
final_k(const __nv_bfloat16* __restrict__ hh1hi, const __nv_bfloat16* __restrict__ hh1lo,
        const float* __restrict__ h2,
        const float* __restrict__ e1, const float* __restrict__ e2,
        const float* __restrict__ Bw, float* __restrict__ out)
{
    const int m = blockIdx.x;
    const int o = threadIdx.x;   // 0..255
    __shared__ float s1[8], s2[8];
    if (o < 5) { s1[o] = e1[m * 8 + o]; s2[o] = e2[m * 8 + o]; }
    __syncthreads();

    const float* bw = Bw + o * 25;
    float s = 0.f;
    #pragma unroll
    for (int i = 0; i < 5; i++) {
        const float ei = s1[i];
        #pragma unroll
        for (int j = 0; j < 5; j++) s += ei * bw[i * 5 + j] * s2[j];
    }
    const size_t hidx = (size_t)m * 512 + 256 + o;
    const float h1v = __bfloat162float(hh1hi[hidx]) + __bfloat162float(hh1lo[hidx]);
    out[(size_t)m * FOUTx + o] = h1v + h2[(size_t)m * FOUTx + o] + s;
}

// ---------------------------------------------------------------------------
extern "C" void kernel_launch(void* const* d_in, const int* in_sizes, int n_in,
                              void* d_out, int out_size)
{
    const float* feat = (const float*)d_in[0];
    const int*   adj  = (const int*)  d_in[1];
    const float* W    = (const float*)d_in[2];
    const float* W1   = (const float*)d_in[3];
    const float* W2   = (const float*)d_in[4];
    const float* a1   = (const float*)d_in[5];
    const float* a2   = (const float*)d_in[6];
    const float* a12  = (const float*)d_in[7];
    const float* Lw   = (const float*)d_in[8];
    const float* Rw   = (const float*)d_in[9];
    const float* Bw   = (const float*)d_in[10];
    float* out = (float*)d_out;

    float *h2, *Ax, *Ay, *e1, *e2, *S;
    __nv_bfloat16 *hh1hi, *hh1lo, *Shi, *Slo, *Fhi, *Flo, *ghi, *glo;
    __nv_bfloat16 *fRhi, *fRlo, *fahi, *falo;
    __nv_bfloat16 *WW1th, *WW1tl, *W2th, *W2tl, *a12th, *a12tl;
    cudaGetSymbolAddress((void**)&hh1hi, g_hh1hi);
    cudaGetSymbolAddress((void**)&hh1lo, g_hh1lo);
    cudaGetSymbolAddress((void**)&h2, g_h2);
    cudaGetSymbolAddress((void**)&Ax, g_Ax);
    cudaGetSymbolAddress((void**)&Ay, g_Ay);
    cudaGetSymbolAddress((void**)&e1, g_e1);
    cudaGetSymbolAddress((void**)&e2, g_e2);
    cudaGetSymbolAddress((void**)&S,  g_S);
    cudaGetSymbolAddress((void**)&Shi, g_Shi);
    cudaGetSymbolAddress((void**)&Slo, g_Slo);
    cudaGetSymbolAddress((void**)&Fhi, g_Fhi);
    cudaGetSymbolAddress((void**)&Flo, g_Flo);
    cudaGetSymbolAddress((void**)&ghi, g_ghi);
    cudaGetSymbolAddress((void**)&glo, g_glo);
    cudaGetSymbolAddress((void**)&fRhi, g_fRhi);
    cudaGetSymbolAddress((void**)&fRlo, g_fRlo);
    cudaGetSymbolAddress((void**)&fahi, g_fahi);
    cudaGetSymbolAddress((void**)&falo, g_falo);
    cudaGetSymbolAddress((void**)&WW1th, g_WW1th);
    cudaGetSymbolAddress((void**)&WW1tl, g_WW1tl);
    cudaGetSymbolAddress((void**)&W2th, g_W2th);
    cudaGetSymbolAddress((void**)&W2tl, g_W2tl);
    cudaGetSymbolAddress((void**)&a12th, g_a12th);
    cudaGetSymbolAddress((void**)&a12tl, g_a12tl);

    static int smem_set = 0;
    if (!smem_set) {
        cudaFuncSetAttribute(mma_gemm_k<0>, cudaFuncAttributeMaxDynamicSharedMemorySize,
                             AGG_SMEM);
        cudaFuncSetAttribute(mma_gemm_k<1>, cudaFuncAttributeMaxDynamicSharedMemorySize,
                             AGG_SMEM);
        cudaFuncSetAttribute(mma_gemm_k<3>, cudaFuncAttributeMaxDynamicSharedMemorySize,
                             AGG_SMEM);
        smem_set = 1;
    }

    const dim3 blk(256);
    const dim3 tb(32, 8);

    // weight transposes + splits (tiny); [W^T ; W1^T] fused
    tsplit_k<<<dim3(FOUTx/32, FINx/32), tb>>>(W,  WW1th,            WW1tl,            FINx, FOUTx);
    tsplit_k<<<dim3(FOUTx/32, FINx/32), tb>>>(W1, WW1th + 256*FINx, WW1tl + 256*FINx, FINx, FOUTx);
    tsplit_k<<<dim3(FOUTx/32, FINx/32), tb>>>(W2, W2th, W2tl, FINx, FOUTx);
    tsplit_k<<<dim3(FOUTx/32, FOUTx/32), tb>>>(a12, a12th, a12tl, FOUTx, FOUTx);

    // feat: transposed split + row-major split in one kernel
    transpose_split_k<<<dim3(NN/32, FINx/32, Bn), tb>>>(feat, Fhi, Flo, fRhi, fRlo);

    // [h | h1] = feat @ [W | W1]  (hi/lo only)
    mma_gemm_k<3><<<dim3(512/128, MTOT/128, 1), blk, AGG_SMEM>>>(
        fRhi, fRlo, WW1th, WW1tl, nullptr, FINx, FINx, FINx, MTOT, 512, 512,
        nullptr, nullptr, nullptr, hh1hi, hh1lo);

    // Ax, Ay, e1  (h reconstructed from hi/lo)
    small1_k<<<MTOT/8, 256>>>(hh1hi, hh1lo, feat, a1, a2, Lw, Ax, Ay, e1);

    // g = h @ a12  (hi/lo only)
    mma_gemm_k<3><<<dim3(FOUTx/128, MTOT/128, 1), blk, AGG_SMEM>>>(
        hh1hi, hh1lo, a12th, a12tl, nullptr, FOUTx, 512, FOUTx, MTOT, FOUTx, FOUTx,
        nullptr, nullptr, nullptr, ghi, glo);

    // S = leaky(Ax+Ay+g.h^T) masked
    mma_gemm_k<1><<<dim3(NN/128, NN/128, Bn), blk, AGG_SMEM>>>(
        ghi, glo, hh1hi, hh1lo, S, FOUTx, FOUTx, 512, NN, NN, NN,
        Ax, Ay, adj, nullptr, nullptr);

    // row softmax -> bf16 hi/lo probs
    softmax_k<<<MTOT, 256>>>(S, Shi, Slo);

    // feat_agg = P @ feat  (hi/lo only)
    mma_gemm_k<3><<<dim3(FINx/128, NN/128, Bn), blk, AGG_SMEM>>>(
        Shi, Slo, Fhi, Flo, nullptr, NN, NN, NN, NN, FINx, FINx,
        nullptr, nullptr, nullptr, fahi, falo);

    // h2 = fa @ W2 ; e2
    mma_gemm_k<0><<<dim3(FOUTx/128, MTOT/128, 1), blk, AGG_SMEM>>>(
        fahi, falo, W2th, W2tl, h2, FINx, FINx, FINx, MTOT, FOUTx, FOUTx,
        nullptr, nullptr, nullptr, nullptr, nullptr);
    small2_k<<<MTOT/8, 256>>>(fahi, falo, Rw, e2);

    // out = h1 + h2 + bilinear(e1, B_w, e2)
    final_k<<<MTOT, 256>>>(hh1hi, hh1lo, h2, e1, e2, Bw, out);
}